// round 13
// baseline (speedup 1.0000x reference)
#include <cuda_runtime.h>
#include <cuda_fp16.h>
#include <math.h>
#include <cstdint>

#define B_ROWS 16384
#define H_DIM  512
#define K_DIM  512
#define N_OUT  1536   // 3*H

// fp16 copies of inputs (converted once per launch) + fp16 GEMM scratch.
__device__ __half g_xh[(size_t)B_ROWS * K_DIM];
__device__ __half g_hh[(size_t)B_ROWS * K_DIM];
__device__ __half g_wih[(size_t)N_OUT * K_DIM];
__device__ __half g_whh[(size_t)N_OUT * K_DIM];
__device__ __half g_xt[(size_t)B_ROWS * N_OUT];
__device__ __half g_ht[(size_t)B_ROWS * N_OUT];

// ─────────────── fp32 -> fp16 conversion (balanced 1-D grid) ───────────────
__global__ __launch_bounds__(256) void convert_kernel(
    const float4* __restrict__ x, const float4* __restrict__ hx,
    const float4* __restrict__ Wi, const float4* __restrict__ Wh)
{
    const int bid = blockIdx.x;
    const float4* __restrict__ src;
    __half* dst;
    int base, cnt;
    if (bid < 1024)      { src = x;  dst = g_xh;  base = bid * 2048;          cnt = 2048; }
    else if (bid < 2048) { src = hx; dst = g_hh;  base = (bid - 1024) * 2048; cnt = 2048; }
    else if (bid < 2176) { src = Wi; dst = g_wih; base = (bid - 2048) * 1536; cnt = 1536; }
    else                 { src = Wh; dst = g_whh; base = (bid - 2176) * 1536; cnt = 1536; }

    uint2* __restrict__ d2 = (uint2*)dst;
    for (int i = threadIdx.x; i < cnt; i += 256) {
        const int idx = base + i;
        float4 v = src[idx];
        __half2 lo = __floats2half2_rn(v.x, v.y);
        __half2 hi = __floats2half2_rn(v.z, v.w);
        uint2 o;
        o.x = *(uint32_t*)&lo;
        o.y = *(uint32_t*)&hi;
        d2[idx] = o;
    }
}

// ─────────────── GEMM tiling (unchanged from R12) ───────────────
#define BM 128
#define BN 128
#define BK 64
#define PITCH 72
#define A_BYTES (BM * PITCH * 2)
#define STAGE_BYTES (2 * A_BYTES)
#define NSTAGE 2
#define SMEM_BYTES (NSTAGE * STAGE_BYTES)
#define KSTAGES (K_DIM / BK)
#define NTHREADS 128

__device__ __forceinline__ void cp_async16(uint32_t dst, const void* src) {
    asm volatile("cp.async.cg.shared.global [%0], [%1], 16;"
                 :: "r"(dst), "l"(src) : "memory");
}
#define CP_COMMIT() asm volatile("cp.async.commit_group;" ::: "memory")
#define CP_WAIT(n)  asm volatile("cp.async.wait_group %0;" :: "n"(n) : "memory")

__device__ __forceinline__ uint32_t smem_to_u32(const void* p) {
    uint32_t a;
    asm("{ .reg .u64 t; cvta.to.shared.u64 t, %1; cvt.u32.u64 %0, t; }"
        : "=r"(a) : "l"(p));
    return a;
}

__device__ __forceinline__ void ldsm_x4(uint32_t& r0, uint32_t& r1,
                                        uint32_t& r2, uint32_t& r3, uint32_t addr) {
    asm volatile("ldmatrix.sync.aligned.m8n8.x4.shared.b16 {%0,%1,%2,%3}, [%4];"
                 : "=r"(r0), "=r"(r1), "=r"(r2), "=r"(r3) : "r"(addr));
}

__device__ __forceinline__ void mma_f16(
    float& c0, float& c1, float& c2, float& c3,
    uint32_t a0, uint32_t a1, uint32_t a2, uint32_t a3,
    uint32_t b0, uint32_t b1)
{
    asm volatile(
        "mma.sync.aligned.m16n8k16.row.col.f32.f16.f16.f32 "
        "{%0,%1,%2,%3}, {%4,%5,%6,%7}, {%8,%9}, {%0,%1,%2,%3};"
        : "+f"(c0), "+f"(c1), "+f"(c2), "+f"(c3)
        : "r"(a0), "r"(a1), "r"(a2), "r"(a3), "r"(b0), "r"(b1));
}

__device__ __forceinline__ void load_stage(
    uint32_t a_smem, uint32_t b_smem,
    const __half* __restrict__ A, const __half* __restrict__ W,
    int m0, int n0, int k0, int tid)
{
#pragma unroll
    for (int i = 0; i < 8; i++) {
        int c   = i * NTHREADS + tid;
        int row = c >> 3;
        int ch  = c & 7;
        uint32_t off = (uint32_t)(row * PITCH + ch * 8) * 2u;
        cp_async16(a_smem + off, A + (size_t)(m0 + row) * K_DIM + k0 + ch * 8);
        cp_async16(b_smem + off, W + (size_t)(n0 + row) * K_DIM + k0 + ch * 8);
    }
}

__global__ __launch_bounds__(NTHREADS, 3) void gemm_tc_kernel(
    const float* __restrict__ bi, const float* __restrict__ bh)
{
    extern __shared__ float sm[];
    const int tid = threadIdx.x;
    const int which = blockIdx.z;
    const __half* __restrict__ A    = which ? g_hh  : g_xh;
    const __half* __restrict__ W    = which ? g_whh : g_wih;
    const float*  __restrict__ bias = which ? bh : bi;
    __half* __restrict__ C          = which ? g_ht : g_xt;
    const int m0 = blockIdx.y * BM;
    const int n0 = blockIdx.x * BN;

    const uint32_t sm32 = smem_to_u32(sm);

    const int wid  = tid >> 5;
    const int lane = tid & 31;
    const int wr   = wid >> 1;
    const int wc   = wid & 1;
    const int g    = lane >> 2;
    const int t    = lane & 3;

    const uint32_t aOff = ((uint32_t)((wr * 64 + (lane & 15)) * PITCH
                                      + (lane >> 4) * 8)) * 2u;
    const uint32_t bOff = ((uint32_t)((wc * 64 + ((lane >> 4) & 1) * 8 + (lane & 7)) * PITCH
                                      + ((lane >> 3) & 1) * 8)) * 2u + A_BYTES;

    float c[4][8][4];
#pragma unroll
    for (int mt = 0; mt < 4; mt++)
#pragma unroll
        for (int nt = 0; nt < 8; nt++)
#pragma unroll
            for (int r = 0; r < 4; r++) c[mt][nt][r] = 0.f;

    load_stage(sm32, sm32 + A_BYTES, A, W, m0, n0, 0, tid);
    CP_COMMIT();

    for (int ks = 0; ks < KSTAGES; ks++) {
        CP_WAIT(0);
        __syncthreads();

        if (ks + 1 < KSTAGES) {
            const uint32_t sbase = sm32 + (uint32_t)((ks + 1) & 1) * STAGE_BYTES;
            load_stage(sbase, sbase + A_BYTES, A, W, m0, n0, (ks + 1) * BK, tid);
            CP_COMMIT();
        }

        const uint32_t buf = sm32 + (uint32_t)(ks & 1) * STAGE_BYTES;
        const uint32_t aBase = buf + aOff;
        const uint32_t bBase = buf + bOff;

#pragma unroll
        for (int k16 = 0; k16 < 4; k16++) {
            const uint32_t kOff = (uint32_t)(k16 * 16) * 2u;
            uint32_t a[4][4];
#pragma unroll
            for (int mt = 0; mt < 4; mt++)
                ldsm_x4(a[mt][0], a[mt][1], a[mt][2], a[mt][3],
                        aBase + (uint32_t)(mt * 16 * PITCH) * 2u + kOff);
#pragma unroll
            for (int ntp = 0; ntp < 4; ntp++) {
                uint32_t b0, b1, b2, b3;
                ldsm_x4(b0, b1, b2, b3,
                        bBase + (uint32_t)(ntp * 16 * PITCH) * 2u + kOff);
#pragma unroll
                for (int mt = 0; mt < 4; mt++) {
                    mma_f16(c[mt][2*ntp][0], c[mt][2*ntp][1],
                            c[mt][2*ntp][2], c[mt][2*ntp][3],
                            a[mt][0], a[mt][1], a[mt][2], a[mt][3], b0, b1);
                    mma_f16(c[mt][2*ntp+1][0], c[mt][2*ntp+1][1],
                            c[mt][2*ntp+1][2], c[mt][2*ntp+1][3],
                            a[mt][0], a[mt][1], a[mt][2], a[mt][3], b2, b3);
                }
            }
        }
    }

#pragma unroll
    for (int mt = 0; mt < 4; mt++) {
        const int row = m0 + wr * 64 + mt * 16 + g;
#pragma unroll
        for (int nt = 0; nt < 8; nt++) {
            const int col = n0 + wc * 64 + nt * 8 + 2 * t;
            const float b0 = __ldg(&bias[col]), b1 = __ldg(&bias[col + 1]);
            *(__half2*)&C[(size_t)row * N_OUT + col] =
                __floats2half2_rn(c[mt][nt][0] + b0, c[mt][nt][1] + b1);
            *(__half2*)&C[(size_t)(row + 8) * N_OUT + col] =
                __floats2half2_rn(c[mt][nt][2] + b0, c[mt][nt][3] + b1);
        }
    }
}

// ─────────────── LN/GRU epilogue: one warp per row ───────────────
__device__ __forceinline__ float fast_sigmoid(float x) {
    return 1.f / (1.f + __expf(-x));
}
__device__ __forceinline__ float fast_tanh(float x) {
    return 1.f - 2.f / (__expf(2.f * x) + 1.f);
}
__device__ __forceinline__ float2 h2f(__half2 h) { return __half22float2(h); }
__device__ __forceinline__ __half2 get_h2(const uint4& u, int c) {
    uint32_t w = (c == 0) ? u.x : (c == 1) ? u.y : (c == 2) ? u.z : u.w;
    return *(__half2*)&w;
}
__device__ __forceinline__ void acc_u4(const uint4& u, float& s, float& q) {
#pragma unroll
    for (int c = 0; c < 4; c++) {
        float2 f = h2f(get_h2(u, c));
        s += f.x + f.y;
        q = fmaf(f.x, f.x, q);
        q = fmaf(f.y, f.y, q);
    }
}
__device__ __forceinline__ float wred(float v) {
#pragma unroll
    for (int off = 16; off > 0; off >>= 1)
        v += __shfl_xor_sync(0xffffffffu, v, off);
    return v;
}

// Lane l: gates r = u4 {l, l+32}, gates z = {l+64, l+96}, cand = {l+128, l+160}.
// Outputs: cols [8l, 8l+8) (grp 0) and [256+8l, 256+8l+8) (grp 1).
__global__ __launch_bounds__(256) void epilogue_kernel(
    const float* __restrict__ hx, float* __restrict__ out)
{
    const int warp = threadIdx.x >> 5;
    const int lane = threadIdx.x & 31;
    const int row  = blockIdx.x * 8 + warp;

    const uint4* __restrict__ xr = (const uint4*)(g_xt + (size_t)row * N_OUT);
    const uint4* __restrict__ hr = (const uint4*)(g_ht + (size_t)row * N_OUT);

    uint4 xg[4], hg[4], xc[2], hc[2];
    xg[0] = xr[lane];       xg[1] = xr[lane + 32];
    xg[2] = xr[lane + 64];  xg[3] = xr[lane + 96];
    xc[0] = xr[lane + 128]; xc[1] = xr[lane + 160];
    hg[0] = hr[lane];       hg[1] = hr[lane + 32];
    hg[2] = hr[lane + 64];  hg[3] = hr[lane + 96];
    hc[0] = hr[lane + 128]; hc[1] = hr[lane + 160];

    float s_xg = 0.f, q_xg = 0.f, s_hg = 0.f, q_hg = 0.f;
    float s_xn = 0.f, q_xn = 0.f, s_hn = 0.f, q_hn = 0.f;
#pragma unroll
    for (int i = 0; i < 4; i++) { acc_u4(xg[i], s_xg, q_xg); acc_u4(hg[i], s_hg, q_hg); }
#pragma unroll
    for (int i = 0; i < 2; i++) { acc_u4(xc[i], s_xn, q_xn); acc_u4(hc[i], s_hn, q_hn); }

    s_xg = wred(s_xg); q_xg = wred(q_xg);
    s_hg = wred(s_hg); q_hg = wred(q_hg);
    s_xn = wred(s_xn); q_xn = wred(q_xn);
    s_hn = wred(s_hn); q_hn = wred(q_hn);

    const float inv1024 = 1.f / 1024.f;
    const float inv512  = 1.f / 512.f;
    const float m_xg = s_xg * inv1024;
    const float r_xg = rsqrtf(q_xg * inv1024 - m_xg * m_xg + 1e-5f);
    const float m_hg = s_hg * inv1024;
    const float r_hg = rsqrtf(q_hg * inv1024 - m_hg * m_hg + 1e-5f);
    const float m_xn = s_xn * inv512;
    const float r_xn = rsqrtf(q_xn * inv512 - m_xn * m_xn + 1e-5f);
    const float m_hn = s_hn * inv512;
    const float r_hn = rsqrtf(q_hn * inv512 - m_hn * m_hn + 1e-5f);

    const float4* __restrict__ hx4 = (const float4*)(hx + (size_t)row * H_DIM);
    float4* __restrict__ out4      = (float4*)(out + (size_t)row * H_DIM);

#pragma unroll
    for (int grp = 0; grp < 2; grp++) {
        const uint4 gxr = xg[grp];
        const uint4 gxz = xg[grp + 2];
        const uint4 ghr = hg[grp];
        const uint4 ghz = hg[grp + 2];
        const uint4 gxn = xc[grp];
        const uint4 ghn = hc[grp];
        float nt[8], zs[8];
#pragma unroll
        for (int c = 0; c < 4; c++) {
            float2 fxr = h2f(get_h2(gxr, c));
            float2 fxz = h2f(get_h2(gxz, c));
            float2 fhr = h2f(get_h2(ghr, c));
            float2 fhz = h2f(get_h2(ghz, c));
            float2 fxn = h2f(get_h2(gxn, c));
            float2 fhn = h2f(get_h2(ghn, c));

            float rg0 = fast_sigmoid((fxr.x - m_xg) * r_xg + (fhr.x - m_hg) * r_hg);
            zs[2*c]   = fast_sigmoid((fxz.x - m_xg) * r_xg + (fhz.x - m_hg) * r_hg);
            nt[2*c]   = fast_tanh((fxn.x - m_xn) * r_xn + rg0 * ((fhn.x - m_hn) * r_hn));

            float rg1 = fast_sigmoid((fxr.y - m_xg) * r_xg + (fhr.y - m_hg) * r_hg);
            zs[2*c+1] = fast_sigmoid((fxz.y - m_xg) * r_xg + (fhz.y - m_hg) * r_hg);
            nt[2*c+1] = fast_tanh((fxn.y - m_xn) * r_xn + rg1 * ((fhn.y - m_hn) * r_hn));
        }
        float4 hv0 = hx4[grp * 64 + 2 * lane];
        float4 hv1 = hx4[grp * 64 + 2 * lane + 1];
        float4 o0, o1;
        o0.x = zs[0] * hv0.x + (1.f - zs[0]) * nt[0];
        o0.y = zs[1] * hv0.y + (1.f - zs[1]) * nt[1];
        o0.z = zs[2] * hv0.z + (1.f - zs[2]) * nt[2];
        o0.w = zs[3] * hv0.w + (1.f - zs[3]) * nt[3];
        o1.x = zs[4] * hv1.x + (1.f - zs[4]) * nt[4];
        o1.y = zs[5] * hv1.y + (1.f - zs[5]) * nt[5];
        o1.z = zs[6] * hv1.z + (1.f - zs[6]) * nt[6];
        o1.w = zs[7] * hv1.w + (1.f - zs[7]) * nt[7];
        out4[grp * 64 + 2 * lane]     = o0;
        out4[grp * 64 + 2 * lane + 1] = o1;
    }
}

extern "C" void kernel_launch(void* const* d_in, const int* in_sizes, int n_in,
                              void* d_out, int out_size)
{
    const float* x     = (const float*)d_in[0];
    const float* hx    = (const float*)d_in[1];
    const float* W_i2h = (const float*)d_in[2];
    const float* b_i2h = (const float*)d_in[3];
    const float* W_h2h = (const float*)d_in[4];
    const float* b_h2h = (const float*)d_in[5];
    float* out = (float*)d_out;

    cudaFuncSetAttribute(gemm_tc_kernel,
                         cudaFuncAttributeMaxDynamicSharedMemorySize, SMEM_BYTES);

    convert_kernel<<<2304, 256>>>((const float4*)x, (const float4*)hx,
                                  (const float4*)W_i2h, (const float4*)W_h2h);

    dim3 grid(N_OUT / BN, B_ROWS / BM, 2);   // (12, 128, 2)
    gemm_tc_kernel<<<grid, NTHREADS, SMEM_BYTES>>>(b_i2h, b_h2h);
    epilogue_kernel<<<B_ROWS / 8, 256>>>(hx, out);
}